// round 11
// baseline (speedup 1.0000x reference)
#include <cuda_runtime.h>
#include <math.h>
#include <math_constants.h>

#define H_ 512
#define W_ 1024
#define HW_ (H_*W_)
#define B_ 2
#define C_ 34
#define TOPK_ 200
#define MAXK_ 5888
#define SURV_ 4096

// ---------------- scratch (self-cleaning: last consumer resets) ----------------
__device__ float g_vote[B_*HW_];
__device__ float g_m[B_*HW_];
__device__ float g_s[B_*HW_];
__device__ int   g_cnt[B_];
__device__ float g_kval[B_*MAXK_];
__device__ int   g_kidx[B_*MAXK_];
__device__ float g_tv[B_*TOPK_];
__device__ int   g_ti[B_*TOPK_];
__device__ float g_ca[B_*TOPK_];
__device__ float g_cb[B_*TOPK_];
__device__ float g_cc[B_*TOPK_];
__device__ int   g_counts[B_*TOPK_*C_];
__device__ int   g_cls[B_*TOPK_];
__device__ float g_psum[B_*TOPK_];
__device__ int   g_tcnt[B_];
__device__ int   g_tlist[B_*HW_];
__device__ float g_sfv[B_*SURV_];
__device__ int   g_sfi[B_*SURV_];
__device__ int   g_doneD, g_doneE;

// ---------------- K1: seg (scalar branch-free) + things compaction fold ----------------
__global__ __launch_bounds__(256) void k_seg(const float* __restrict__ logits,
                                             float* __restrict__ o_seg,
                                             float* __restrict__ o_inst) {
    int b = blockIdx.y;
    int tid = threadIdx.x;
    int pix = blockIdx.x * 256 + tid;
    const float* base = logits + (size_t)b * C_ * HW_ + pix;
    float v[C_];
    #pragma unroll
    for (int c = 0; c < C_; c++) v[c] = base[(size_t)c * HW_];
    float m = v[0]; int bi = 0;
    #pragma unroll
    for (int c = 1; c < C_; c++) if (v[c] > m) { m = v[c]; bi = c; }
    float s = 0.f;
    #pragma unroll
    for (int c = 0; c < C_; c++) s += expf(v[c] - m);
    int idx = b * HW_ + pix;
    o_seg[idx] = (float)bi;
    g_m[idx] = m;
    g_s[idx] = s;
    o_inst[idx] = 0.f;             // things px overwritten later by argmin
    // ---- things compaction (bi in [24,33]) ----
    bool things = (bi >= 24) && (bi <= 33);
    unsigned ball = __ballot_sync(0xffffffffu, things);
    if (ball == 0) return;
    int lane = tid & 31;
    int leader = __ffs(ball) - 1;
    int prefix = __popc(ball & ((1u << lane) - 1u));
    int baseI = 0;
    if (lane == leader) baseI = atomicAdd(&g_tcnt[b], __popc(ball));
    baseI = __shfl_sync(0xffffffffu, baseI, leader);
    if (things) g_tlist[b * HW_ + baseI + prefix] = pix;
}

// ---------------- K2: vote map (exact op order) ----------------
__global__ __launch_bounds__(256) void k_vote(const float* __restrict__ reg) {
    __shared__ float2 S[18][43];
    int b = blockIdx.z;
    int ox0 = blockIdx.x * 32, oy0 = blockIdx.y * 8;
    const float* r0 = reg + (size_t)b * 2 * HW_;
    const float* r1 = r0 + HW_;
    int tid = threadIdx.y * 32 + threadIdx.x;
    for (int t = tid; t < 18 * 42; t += 256) {
        int rr = t / 42, cc = t % 42;
        int gy = oy0 + rr - 5, gx = ox0 + cc - 5;
        float vx = 0.f, vy = 0.f;
        if (gy >= 0 && gy < H_ && gx >= 0 && gx < W_) {
            int q = gy * W_ + gx;
            vx = r0[q]; vy = r1[q];
        }
        S[rr][cc] = make_float2(vx, vy);
    }
    __syncthreads();
    int tx = threadIdx.x, ty = threadIdx.y;
    float acc = 0.f;
    #pragma unroll
    for (int i = 0; i < 11; i++) {
        #pragma unroll
        for (int j = 0; j < 11; j++) {
            const int di = i - 5, dj = j - 5;
            if (di*di + dj*dj <= 25) {
                float2 v = S[ty + i][tx + j];
                float dx = __fsub_rn((float)dj, v.x);
                float dy = __fsub_rn((float)di, v.y);
                float t2 = __fadd_rn(__fmul_rn(dx, dx), __fmul_rn(dy, dy));
                acc = __fadd_rn(acc, __fsqrt_rn(t2));
            }
        }
    }
    float t = __fdiv_rn(acc, 81.0f);
    g_vote[b * HW_ + (oy0 + ty) * W_ + ox0 + tx] = __fadd_rn(-t, -1.0f);
}

// ---------------- K3: 7x7 max-pool + keep + center_map + candidate list ----------------
__global__ __launch_bounds__(256) void k_pool(float thrF, float* __restrict__ o_cmap) {
    __shared__ float T[14][39];
    int b = blockIdx.z;
    int ox0 = blockIdx.x * 32, oy0 = blockIdx.y * 8;
    int tid = threadIdx.y * 32 + threadIdx.x;
    for (int t = tid; t < 14 * 38; t += 256) {
        int rr = t / 38, cc = t % 38;
        int gy = oy0 + rr - 3, gx = ox0 + cc - 3;
        T[rr][cc] = (gy >= 0 && gy < H_ && gx >= 0 && gx < W_)
                    ? g_vote[b * HW_ + gy * W_ + gx] : -CUDART_INF_F;
    }
    __syncthreads();
    int tx = threadIdx.x, ty = threadIdx.y;
    float v = T[ty + 3][tx + 3];
    float m = -CUDART_INF_F;
    #pragma unroll
    for (int i = 0; i < 7; i++)
        #pragma unroll
        for (int j = 0; j < 7; j++)
            m = fmaxf(m, T[ty + i][tx + j]);
    bool keep = (m == v) && (v > thrF);
    int pix = (oy0 + ty) * W_ + ox0 + tx;
    o_cmap[b * HW_ + pix] = keep ? v : 0.f;
    if (keep) {
        int p = atomicAdd(&g_cnt[b], 1);
        if (p < MAXK_) { g_kval[b * MAXK_ + p] = v; g_kidx[b * MAXK_ + p] = pix; }
    }
}

// ---------------- K4: radix-select top-200 (parallel bin scan) + rank + centers ----------------
// All candidate votes are negative floats: ascending uint bits == descending float.
__global__ __launch_bounds__(256) void k_select(const float* __restrict__ o_cmap,
                                                float* __restrict__ o_cent,
                                                float* __restrict__ o_tv) {
    __shared__ float sv[MAXK_];
    __shared__ int   si[MAXK_];
    __shared__ unsigned hist[256];
    __shared__ unsigned wsum[8];
    __shared__ unsigned sh_pref, sh_want;
    __shared__ int sh_scnt;
    int b = blockIdx.x;
    int tid = threadIdx.x;
    int lane = tid & 31, wid = tid >> 5;
    int n = g_cnt[b];
    if (n > MAXK_) n = MAXK_;
    for (int i = tid; i < n; i += 256) {
        sv[i] = g_kval[b * MAXK_ + i];
        si[i] = g_kidx[b * MAXK_ + i];
    }
    if (tid == 0) { sh_scnt = 0; sh_want = TOPK_; }
    __syncthreads();

    // ---- exact threshold key T (200th smallest uint key) ----
    unsigned T;
    if (n <= TOPK_) {
        T = 0xFFFFFFFFu;
    } else {
        unsigned prefmask = 0, prefval = 0;
        for (int round = 0; round < 4; round++) {
            int shift = 24 - 8 * round;
            hist[tid] = 0;
            __syncthreads();
            for (int i = tid; i < n; i += 256) {
                unsigned u = __float_as_uint(sv[i]);
                if ((u & prefmask) == prefval)
                    atomicAdd(&hist[(u >> shift) & 255], 1u);
            }
            __syncthreads();
            // block-wide inclusive scan over 256 bins (1 bin/thread)
            unsigned h = hist[tid];
            unsigned x = h;
            #pragma unroll
            for (int off = 1; off < 32; off <<= 1) {
                unsigned y = __shfl_up_sync(0xffffffffu, x, off);
                if (lane >= off) x += y;
            }
            if (lane == 31) wsum[wid] = x;
            __syncthreads();
            if (tid == 0) {
                unsigned c = 0;
                #pragma unroll
                for (int w = 0; w < 8; w++) { unsigned t = wsum[w]; wsum[w] = c; c += t; }
            }
            __syncthreads();
            unsigned incl = x + wsum[wid];
            unsigned excl = incl - h;
            unsigned want = sh_want;
            __syncthreads();                 // all reads of sh_want done
            if (excl < want && want <= incl) {   // exactly one thread
                sh_pref = prefval | ((unsigned)tid << shift);
                sh_want = want - excl;
            }
            __syncthreads();
            prefval = sh_pref;
            prefmask |= (0xFFu << shift);
        }
        T = prefval;
    }

    // ---- collect survivors (key <= T) ----
    for (int i = tid; i < n; i += 256) {
        unsigned u = __float_as_uint(sv[i]);
        if (u <= T) {
            int p = atomicAdd(&sh_scnt, 1);
            if (p < SURV_) { g_sfv[b * SURV_ + p] = sv[i]; g_sfi[b * SURV_ + p] = si[i]; }
        }
    }
    __syncthreads();
    int s = sh_scnt;
    if (s > SURV_) s = SURV_;
    for (int i = tid; i < s; i += 256) {
        sv[i] = g_sfv[b * SURV_ + i];
        si[i] = g_sfi[b * SURV_ + i];
    }
    __syncthreads();

    // ---- exact rank among survivors (value desc, index asc — jax tie rule) ----
    for (int i = tid; i < s; i += 256) {
        unsigned ui = __float_as_uint(sv[i]);
        int idi = si[i];
        int r = 0;
        for (int j = 0; j < s; j++) {
            unsigned uj = __float_as_uint(sv[j]);
            r += (uj < ui) || (uj == ui && si[j] < idi);
        }
        if (r < TOPK_) { g_tv[b * TOPK_ + r] = sv[i]; g_ti[b * TOPK_ + r] = idi; }
    }
    __syncthreads();

    // ---- -inf fill (jax pads lowest-index non-keep positions) ----
    int nk = (n < TOPK_) ? n : TOPK_;
    if (tid == 0 && nk < TOPK_) {
        const float* cm = o_cmap + (size_t)b * HW_;
        int slot = nk;
        for (int idx = 0; idx < HW_ && slot < TOPK_; idx++) {
            if (cm[idx] == 0.f) {
                g_tv[b * TOPK_ + slot] = -CUDART_INF_F;
                g_ti[b * TOPK_ + slot] = idx;
                slot++;
            }
        }
    }
    __syncthreads();

    // ---- centers + argmin coefficients; reset g_cnt for next graph replay ----
    if (tid < TOPK_) {
        float v = g_tv[b * TOPK_ + tid];
        int id = g_ti[b * TOPK_ + tid];
        int ys = id / W_, xs = id % W_;
        o_cent[(b * TOPK_ + tid) * 2 + 0] = (float)ys;
        o_cent[(b * TOPK_ + tid) * 2 + 1] = (float)xs;
        o_tv[b * TOPK_ + tid] = v;
        bool valid = isfinite(v);
        float cx = valid ? (float)xs : 1e9f;
        float cy = valid ? (float)ys : 1e9f;
        g_ca[b * TOPK_ + tid] = -2.f * cx;
        g_cb[b * TOPK_ + tid] = -2.f * cy;
        g_cc[b * TOPK_ + tid] = cx * cx + cy * cy;
    }
    if (tid == 0) g_cnt[b] = 0;
}

// ---------------- K5: argmin over 200 centers + fused histogram + (last block) class/size ----------------
#define ABLK_ (HW_ / 256)
__global__ __launch_bounds__(256) void k_argmin(const float* __restrict__ reg,
                                                const float* __restrict__ o_seg,
                                                float* __restrict__ o_inst,
                                                float* __restrict__ o_cls,
                                                float* __restrict__ o_size) {
    __shared__ float4 Ctr[TOPK_];
    int b = blockIdx.y;
    int tid = threadIdx.x;
    if (tid < TOPK_)
        Ctr[tid] = make_float4(g_ca[b * TOPK_ + tid], g_cb[b * TOPK_ + tid],
                               g_cc[b * TOPK_ + tid], 0.f);
    __syncthreads();
    int n = g_tcnt[b];
    int i = blockIdx.x * 256 + tid;
    int inst = 0, cls = 0;
    if (i < n) {
        int pix = g_tlist[b * HW_ + i];
        int y = pix >> 10, x = pix & 1023;
        const float* r0 = reg + (size_t)b * 2 * HW_;
        float px = (float)(x + 1) - r0[pix];
        float py = (float)(y + 1) - r0[HW_ + pix];
        float best = CUDART_INF_F; int bi = 0;
        #pragma unroll 10
        for (int k = 0; k < TOPK_; k++) {
            float4 c = Ctr[k];
            float t = __fmaf_rn(c.x, px, __fmaf_rn(c.y, py, c.z));
            if (t < best) { best = t; bi = k; }
        }
        o_inst[b * HW_ + pix] = (float)(bi + 1);
        inst = bi + 1;
        cls = (int)o_seg[b * HW_ + pix];
    }
    int key = inst * 64 + cls;
    unsigned peers = __match_any_sync(0xffffffffu, key);
    int lane = tid & 31;
    if (inst > 0 && lane == (__ffs(peers) - 1))
        atomicAdd(&g_counts[(b * TOPK_ + inst - 1) * C_ + cls], __popc(peers));
    // ---- last-block fold: class argmax + size; reset counts + ticket ----
    __syncthreads();
    __shared__ int isLast;
    __threadfence();
    if (tid == 0) isLast = (atomicAdd(&g_doneD, 1) == ABLK_ * B_ - 1);
    __syncthreads();
    if (!isLast) return;
    __threadfence();
    for (int t = tid; t < B_ * TOPK_; t += 256) {
        int* base = &g_counts[t * C_];
        int sum = 0, best = -1, bi = 0;
        #pragma unroll
        for (int c = 0; c < C_; c++) {
            int cnt = base[c];
            sum += cnt;
            if (cnt > best) { best = cnt; bi = c; }
        }
        o_cls[t]  = (float)bi;
        o_size[t] = (float)sum;
        g_cls[t]  = bi;
        #pragma unroll
        for (int c = 0; c < C_; c++) base[c] = 0;   // self-clean
    }
    if (tid == 0) g_doneD = 0;                       // self-clean
}

// ---------------- K6: per-instance prob sums + (last block) finalize ----------------
__global__ __launch_bounds__(256) void k_prob(const float* __restrict__ logits,
                                              const float* __restrict__ o_inst,
                                              const float* __restrict__ o_size,
                                              float* __restrict__ o_prob) {
    int b = blockIdx.y;
    int n = g_tcnt[b];
    int tid = threadIdx.x;
    int i = blockIdx.x * 256 + tid;
    int inst = 0;
    float p = 0.f;
    if (i < n) {
        int pix = g_tlist[b * HW_ + i];
        int idx = b * HW_ + pix;
        inst = (int)o_inst[idx];
        int c = g_cls[b * TOPK_ + inst - 1];
        float l = logits[((size_t)b * C_ + c) * HW_ + pix];
        p = expf(l - g_m[idx]) / g_s[idx];
    }
    unsigned peers = __match_any_sync(0xffffffffu, inst);
    int lane = tid & 31;
    int leader = __ffs(peers) - 1;
    float tot = 0.f;
    #pragma unroll
    for (int k = 0; k < 32; k++) {
        float pk = __shfl_sync(0xffffffffu, p, k);
        if (peers & (1u << k)) tot += pk;
    }
    if (inst > 0 && lane == leader)
        atomicAdd(&g_psum[b * TOPK_ + inst - 1], tot);
    // ---- last-block fold: finalize; reset psum/tcnt/ticket ----
    __syncthreads();
    __shared__ int isLast;
    __threadfence();
    if (tid == 0) isLast = (atomicAdd(&g_doneE, 1) == ABLK_ * B_ - 1);
    __syncthreads();
    if (!isLast) return;
    __threadfence();
    for (int t = tid; t < B_ * TOPK_; t += 256) {
        o_prob[t] = g_psum[t] / fmaxf(o_size[t], 1.f);
        g_psum[t] = 0.f;                             // self-clean
    }
    if (tid < B_) g_tcnt[tid] = 0;                   // self-clean
    if (tid == 0) g_doneE = 0;                       // self-clean
}

// ---------------- host ----------------
extern "C" void kernel_launch(void* const* d_in, const int* in_sizes, int n_in,
                              void* d_out, int out_size) {
    const float* logits = (const float*)d_in[0];
    const float* regs   = (const float*)d_in[2];
    float* out = (float*)d_out;

    float* o_inst = out;                    // [B, H, W]
    float* o_seg  = out + 2 * HW_;          // [B, H, W]
    float* o_cent = out + 4 * HW_;          // [B, 200, 2]
    float* o_tv   = o_cent + B_ * TOPK_ * 2;// [B, 200]
    float* o_cls  = o_tv   + B_ * TOPK_;    // [B, 200]
    float* o_prob = o_cls  + B_ * TOPK_;    // [B, 200]
    float* o_size = o_prob + B_ * TOPK_;    // [B, 200]
    float* o_cmap = o_size + B_ * TOPK_;    // [B, H, W]

    // Threshold: numpy float32 pairwise sum of (cd*cmask) over 11x11,
    // thr = double(sum)/81.0, compare value = float(-thr - 1.0)
    float a[121];
    for (int i = 0; i < 11; i++)
        for (int j = 0; j < 11; j++) {
            int di = i - 5, dj = j - 5;
            int r2 = di * di + dj * dj;
            a[i * 11 + j] = (r2 <= 25) ? sqrtf((float)r2) : 0.0f;
        }
    float r[8];
    for (int k = 0; k < 8; k++) r[k] = a[k];
    int i = 8;
    for (; i < 120; i += 8)
        for (int k = 0; k < 8; k++) r[k] += a[i + k];
    float res = ((r[0] + r[1]) + (r[2] + r[3])) + ((r[4] + r[5]) + (r[6] + r[7]));
    for (; i < 121; i++) res += a[i];
    double thr = (double)res / 81.0;
    float thrF = (float)(-thr - 1.0);

    k_seg<<<dim3(HW_ / 256, B_), 256>>>(logits, o_seg, o_inst);
    k_vote<<<dim3(W_ / 32, H_ / 8, B_), dim3(32, 8)>>>(regs);
    k_pool<<<dim3(W_ / 32, H_ / 8, B_), dim3(32, 8)>>>(thrF, o_cmap);
    k_select<<<B_, 256>>>(o_cmap, o_cent, o_tv);
    k_argmin<<<dim3(ABLK_, B_), 256>>>(regs, o_seg, o_inst, o_cls, o_size);
    k_prob<<<dim3(ABLK_, B_), 256>>>(logits, o_inst, o_size, o_prob);
}

// round 14
// speedup vs baseline: 1.4970x; 1.4970x over previous
#include <cuda_runtime.h>
#include <math.h>
#include <math_constants.h>

#define H_ 512
#define W_ 1024
#define HW_ (H_*W_)
#define B_ 2
#define C_ 34
#define TOPK_ 200
#define MAXK_ 5888
#define SURV_ 4096

// ---------------- scratch ----------------
__device__ float g_vote[B_*HW_];
__device__ float g_m[B_*HW_];
__device__ float g_s[B_*HW_];
__device__ int   g_cnt[B_];
__device__ float g_kval[B_*MAXK_];
__device__ int   g_kidx[B_*MAXK_];
__device__ float g_tv[B_*TOPK_];
__device__ int   g_ti[B_*TOPK_];
__device__ float g_ca[B_*TOPK_];
__device__ float g_cb[B_*TOPK_];
__device__ float g_cc[B_*TOPK_];
__device__ int   g_counts[B_*TOPK_*C_];
__device__ int   g_cls[B_*TOPK_];
__device__ float g_psum[B_*TOPK_];
__device__ int   g_tcnt[B_];
__device__ int   g_tlist[B_*HW_];
__device__ float g_sfv[B_*SURV_];
__device__ int   g_sfi[B_*SURV_];
__device__ int   g_doneD, g_doneE;

// ---------------- K1: seg — R2 scalar branch-free body (+init fold) ----------------
__global__ __launch_bounds__(256) void k_seg(const float* __restrict__ logits,
                                             float* __restrict__ o_seg) {
    int b = blockIdx.y;
    int tid = threadIdx.x;
    if (blockIdx.x == 0 && b == 0) {   // init fold (consumers are later launches)
        for (int i = tid; i < B_*TOPK_*C_; i += 256) g_counts[i] = 0;
        for (int i = tid; i < B_*TOPK_;    i += 256) g_psum[i] = 0.f;
        if (tid < B_) { g_cnt[tid] = 0; g_tcnt[tid] = 0; }
        if (tid == 0) { g_doneD = 0; g_doneE = 0; }
    }
    int pix = blockIdx.x * 256 + tid;
    const float* base = logits + (size_t)b * C_ * HW_ + pix;
    float v[C_];
    #pragma unroll
    for (int c = 0; c < C_; c++) v[c] = base[(size_t)c * HW_];
    float m = v[0]; int bi = 0;
    #pragma unroll
    for (int c = 1; c < C_; c++) if (v[c] > m) { m = v[c]; bi = c; }
    float s = 0.f;
    #pragma unroll
    for (int c = 0; c < C_; c++) s += expf(v[c] - m);
    int idx = b * HW_ + pix;
    o_seg[idx] = (float)bi;
    g_m[idx] = m;
    g_s[idx] = s;
}

// ---------------- K2: vote map (exact op order) ----------------
__global__ __launch_bounds__(256) void k_vote(const float* __restrict__ reg) {
    __shared__ float2 S[18][43];
    int b = blockIdx.z;
    int ox0 = blockIdx.x * 32, oy0 = blockIdx.y * 8;
    const float* r0 = reg + (size_t)b * 2 * HW_;
    const float* r1 = r0 + HW_;
    int tid = threadIdx.y * 32 + threadIdx.x;
    for (int t = tid; t < 18 * 42; t += 256) {
        int rr = t / 42, cc = t % 42;
        int gy = oy0 + rr - 5, gx = ox0 + cc - 5;
        float vx = 0.f, vy = 0.f;
        if (gy >= 0 && gy < H_ && gx >= 0 && gx < W_) {
            int q = gy * W_ + gx;
            vx = r0[q]; vy = r1[q];
        }
        S[rr][cc] = make_float2(vx, vy);
    }
    __syncthreads();
    int tx = threadIdx.x, ty = threadIdx.y;
    float acc = 0.f;
    #pragma unroll
    for (int i = 0; i < 11; i++) {
        #pragma unroll
        for (int j = 0; j < 11; j++) {
            const int di = i - 5, dj = j - 5;
            if (di*di + dj*dj <= 25) {
                float2 v = S[ty + i][tx + j];
                float dx = __fsub_rn((float)dj, v.x);
                float dy = __fsub_rn((float)di, v.y);
                float t2 = __fadd_rn(__fmul_rn(dx, dx), __fmul_rn(dy, dy));
                acc = __fadd_rn(acc, __fsqrt_rn(t2));
            }
        }
    }
    float t = __fdiv_rn(acc, 81.0f);
    g_vote[b * HW_ + (oy0 + ty) * W_ + ox0 + tx] = __fadd_rn(-t, -1.0f);
}

// ---------------- K3: 7x7 max-pool + keep + candidate list + things fold ----------------
__global__ __launch_bounds__(256) void k_pool(float thrF,
                                              const float* __restrict__ o_seg,
                                              float* __restrict__ o_cmap,
                                              float* __restrict__ o_inst) {
    __shared__ float T[14][39];
    int b = blockIdx.z;
    int ox0 = blockIdx.x * 32, oy0 = blockIdx.y * 8;
    int tid = threadIdx.y * 32 + threadIdx.x;
    for (int t = tid; t < 14 * 38; t += 256) {
        int rr = t / 38, cc = t % 38;
        int gy = oy0 + rr - 3, gx = ox0 + cc - 3;
        T[rr][cc] = (gy >= 0 && gy < H_ && gx >= 0 && gx < W_)
                    ? g_vote[b * HW_ + gy * W_ + gx] : -CUDART_INF_F;
    }
    __syncthreads();
    int tx = threadIdx.x, ty = threadIdx.y;
    float v = T[ty + 3][tx + 3];
    float m = -CUDART_INF_F;
    #pragma unroll
    for (int i = 0; i < 7; i++)
        #pragma unroll
        for (int j = 0; j < 7; j++)
            m = fmaxf(m, T[ty + i][tx + j]);
    bool keep = (m == v) && (v > thrF);
    int pix = (oy0 + ty) * W_ + ox0 + tx;
    o_cmap[b * HW_ + pix] = keep ? v : 0.f;
    if (keep) {
        int p = atomicAdd(&g_cnt[b], 1);
        if (p < MAXK_) { g_kval[b * MAXK_ + p] = v; g_kidx[b * MAXK_ + p] = pix; }
    }
    // ---- things fold: 1 px/thread, same pixel as pool output ----
    float sc = o_seg[b * HW_ + pix];
    bool things = (sc > 23.99f) && (sc <= 33.0f);
    o_inst[b * HW_ + pix] = 0.f;           // things px overwritten later by argmin
    unsigned ball = __ballot_sync(0xffffffffu, things);
    if (ball == 0) return;
    int lane = tid & 31;
    int leader = __ffs(ball) - 1;
    int prefix = __popc(ball & ((1u << lane) - 1u));
    int baseI = 0;
    if (lane == leader) baseI = atomicAdd(&g_tcnt[b], __popc(ball));
    baseI = __shfl_sync(0xffffffffu, baseI, leader);
    if (things) g_tlist[b * HW_ + baseI + prefix] = pix;
}

// ---------------- K4: radix-select top-200 (1024 threads) + rank + centers ----------------
// All candidate votes are negative floats: ascending uint bits == descending float.
__global__ __launch_bounds__(1024) void k_select(const float* __restrict__ o_cmap,
                                                 float* __restrict__ o_cent,
                                                 float* __restrict__ o_tv) {
    __shared__ float sv[MAXK_];
    __shared__ int   si[MAXK_];
    __shared__ unsigned hist[256];
    __shared__ unsigned wsum[8];
    __shared__ unsigned sh_pref, sh_want;
    __shared__ int sh_scnt;
    int b = blockIdx.x;
    int tid = threadIdx.x;
    int lane = tid & 31, wid = tid >> 5;
    int n = g_cnt[b];
    if (n > MAXK_) n = MAXK_;
    for (int i = tid; i < n; i += 1024) {
        sv[i] = g_kval[b * MAXK_ + i];
        si[i] = g_kidx[b * MAXK_ + i];
    }
    if (tid == 0) { sh_scnt = 0; sh_want = TOPK_; }
    __syncthreads();

    // ---- exact threshold key T (200th smallest uint key) ----
    unsigned T;
    if (n <= TOPK_) {
        T = 0xFFFFFFFFu;
    } else {
        unsigned prefmask = 0, prefval = 0;
        for (int round = 0; round < 4; round++) {
            int shift = 24 - 8 * round;
            if (tid < 256) hist[tid] = 0;
            __syncthreads();
            for (int i = tid; i < n; i += 1024) {
                unsigned u = __float_as_uint(sv[i]);
                if ((u & prefmask) == prefval)
                    atomicAdd(&hist[(u >> shift) & 255], 1u);
            }
            __syncthreads();
            // 256-thread cooperative inclusive scan over the bins
            unsigned h = 0, x = 0;
            if (tid < 256) {
                h = hist[tid];
                x = h;
                #pragma unroll
                for (int off = 1; off < 32; off <<= 1) {
                    unsigned y = __shfl_up_sync(0xffffffffu, x, off);
                    if (lane >= off) x += y;
                }
                if (lane == 31) wsum[wid] = x;
            }
            __syncthreads();
            if (tid == 0) {
                unsigned c = 0;
                #pragma unroll
                for (int w = 0; w < 8; w++) { unsigned t = wsum[w]; wsum[w] = c; c += t; }
            }
            __syncthreads();
            unsigned want = sh_want;
            unsigned incl = 0, excl = 0;
            if (tid < 256) { incl = x + wsum[wid]; excl = incl - h; }
            __syncthreads();                 // all reads of sh_want done
            if (tid < 256 && excl < want && want <= incl) {   // exactly one thread
                sh_pref = prefval | ((unsigned)tid << shift);
                sh_want = want - excl;
            }
            __syncthreads();
            prefval = sh_pref;
            prefmask |= (0xFFu << shift);
        }
        T = prefval;
    }

    // ---- collect survivors (key <= T) ----
    for (int i = tid; i < n; i += 1024) {
        unsigned u = __float_as_uint(sv[i]);
        if (u <= T) {
            int p = atomicAdd(&sh_scnt, 1);
            if (p < SURV_) { g_sfv[b * SURV_ + p] = sv[i]; g_sfi[b * SURV_ + p] = si[i]; }
        }
    }
    __syncthreads();
    int s = sh_scnt;
    if (s > SURV_) s = SURV_;
    for (int i = tid; i < s; i += 1024) {
        sv[i] = g_sfv[b * SURV_ + i];
        si[i] = g_sfi[b * SURV_ + i];
    }
    __syncthreads();

    // ---- exact rank among survivors (value desc, index asc — jax tie rule) ----
    for (int i = tid; i < s; i += 1024) {
        unsigned ui = __float_as_uint(sv[i]);
        int idi = si[i];
        int r = 0;
        for (int j = 0; j < s; j++) {
            unsigned uj = __float_as_uint(sv[j]);
            r += (uj < ui) || (uj == ui && si[j] < idi);
        }
        if (r < TOPK_) { g_tv[b * TOPK_ + r] = sv[i]; g_ti[b * TOPK_ + r] = idi; }
    }
    __syncthreads();

    // ---- -inf fill (jax pads lowest-index non-keep positions) ----
    int nk = (n < TOPK_) ? n : TOPK_;
    if (tid == 0 && nk < TOPK_) {
        const float* cm = o_cmap + (size_t)b * HW_;
        int slot = nk;
        for (int idx = 0; idx < HW_ && slot < TOPK_; idx++) {
            if (cm[idx] == 0.f) {
                g_tv[b * TOPK_ + slot] = -CUDART_INF_F;
                g_ti[b * TOPK_ + slot] = idx;
                slot++;
            }
        }
    }
    __syncthreads();

    // ---- centers + argmin coefficients ----
    if (tid < TOPK_) {
        float v = g_tv[b * TOPK_ + tid];
        int id = g_ti[b * TOPK_ + tid];
        int ys = id / W_, xs = id % W_;
        o_cent[(b * TOPK_ + tid) * 2 + 0] = (float)ys;
        o_cent[(b * TOPK_ + tid) * 2 + 1] = (float)xs;
        o_tv[b * TOPK_ + tid] = v;
        bool valid = isfinite(v);
        float cx = valid ? (float)xs : 1e9f;
        float cy = valid ? (float)ys : 1e9f;
        g_ca[b * TOPK_ + tid] = -2.f * cx;
        g_cb[b * TOPK_ + tid] = -2.f * cy;
        g_cc[b * TOPK_ + tid] = cx * cx + cy * cy;
    }
}

// ---------------- K5: argmin over 200 centers + fused histogram + (last block) class/size ----------------
#define ABLK_ (HW_ / 256)
__global__ __launch_bounds__(256) void k_argmin(const float* __restrict__ reg,
                                                const float* __restrict__ o_seg,
                                                float* __restrict__ o_inst,
                                                float* __restrict__ o_cls,
                                                float* __restrict__ o_size) {
    __shared__ float4 Ctr[TOPK_];
    int b = blockIdx.y;
    int tid = threadIdx.x;
    if (tid < TOPK_)
        Ctr[tid] = make_float4(g_ca[b * TOPK_ + tid], g_cb[b * TOPK_ + tid],
                               g_cc[b * TOPK_ + tid], 0.f);
    __syncthreads();
    int n = g_tcnt[b];
    int i = blockIdx.x * 256 + tid;
    int inst = 0, cls = 0;
    if (i < n) {
        int pix = g_tlist[b * HW_ + i];
        int y = pix >> 10, x = pix & 1023;
        const float* r0 = reg + (size_t)b * 2 * HW_;
        float px = (float)(x + 1) - r0[pix];
        float py = (float)(y + 1) - r0[HW_ + pix];
        float best = CUDART_INF_F; int bi = 0;
        #pragma unroll 10
        for (int k = 0; k < TOPK_; k++) {
            float4 c = Ctr[k];
            float t = __fmaf_rn(c.x, px, __fmaf_rn(c.y, py, c.z));
            if (t < best) { best = t; bi = k; }
        }
        o_inst[b * HW_ + pix] = (float)(bi + 1);
        inst = bi + 1;
        cls = (int)o_seg[b * HW_ + pix];
    }
    int key = inst * 64 + cls;
    unsigned peers = __match_any_sync(0xffffffffu, key);
    int lane = tid & 31;
    if (inst > 0 && lane == (__ffs(peers) - 1))
        atomicAdd(&g_counts[(b * TOPK_ + inst - 1) * C_ + cls], __popc(peers));
    // ---- last-block fold: class argmax + size ----
    __syncthreads();
    __shared__ int isLast;
    __threadfence();
    if (tid == 0) isLast = (atomicAdd(&g_doneD, 1) == ABLK_ * B_ - 1);
    __syncthreads();
    if (!isLast) return;
    __threadfence();
    for (int t = tid; t < B_ * TOPK_; t += 256) {
        const int* base = &g_counts[t * C_];
        int sum = 0, best = -1, bi = 0;
        #pragma unroll
        for (int c = 0; c < C_; c++) {
            int cnt = base[c];
            sum += cnt;
            if (cnt > best) { best = cnt; bi = c; }
        }
        o_cls[t]  = (float)bi;
        o_size[t] = (float)sum;
        g_cls[t]  = bi;
    }
}

// ---------------- K6: per-instance prob sums + (last block) finalize ----------------
__global__ __launch_bounds__(256) void k_prob(const float* __restrict__ logits,
                                              const float* __restrict__ o_inst,
                                              const float* __restrict__ o_size,
                                              float* __restrict__ o_prob) {
    int b = blockIdx.y;
    int n = g_tcnt[b];
    int tid = threadIdx.x;
    int i = blockIdx.x * 256 + tid;
    int inst = 0;
    float p = 0.f;
    if (i < n) {
        int pix = g_tlist[b * HW_ + i];
        int idx = b * HW_ + pix;
        inst = (int)o_inst[idx];
        int c = g_cls[b * TOPK_ + inst - 1];
        float l = logits[((size_t)b * C_ + c) * HW_ + pix];
        p = expf(l - g_m[idx]) / g_s[idx];
    }
    unsigned peers = __match_any_sync(0xffffffffu, inst);
    int lane = tid & 31;
    int leader = __ffs(peers) - 1;
    float tot = 0.f;
    #pragma unroll
    for (int k = 0; k < 32; k++) {
        float pk = __shfl_sync(0xffffffffu, p, k);
        if (peers & (1u << k)) tot += pk;
    }
    if (inst > 0 && lane == leader)
        atomicAdd(&g_psum[b * TOPK_ + inst - 1], tot);
    // ---- last-block fold: finalize inst_seg_prob ----
    __syncthreads();
    __shared__ int isLast;
    __threadfence();
    if (tid == 0) isLast = (atomicAdd(&g_doneE, 1) == ABLK_ * B_ - 1);
    __syncthreads();
    if (!isLast) return;
    __threadfence();
    for (int t = tid; t < B_ * TOPK_; t += 256)
        o_prob[t] = g_psum[t] / fmaxf(o_size[t], 1.f);
}

// ---------------- host ----------------
extern "C" void kernel_launch(void* const* d_in, const int* in_sizes, int n_in,
                              void* d_out, int out_size) {
    const float* logits = (const float*)d_in[0];
    const float* regs   = (const float*)d_in[2];
    float* out = (float*)d_out;

    float* o_inst = out;                    // [B, H, W]
    float* o_seg  = out + 2 * HW_;          // [B, H, W]
    float* o_cent = out + 4 * HW_;          // [B, 200, 2]
    float* o_tv   = o_cent + B_ * TOPK_ * 2;// [B, 200]
    float* o_cls  = o_tv   + B_ * TOPK_;    // [B, 200]
    float* o_prob = o_cls  + B_ * TOPK_;    // [B, 200]
    float* o_size = o_prob + B_ * TOPK_;    // [B, 200]
    float* o_cmap = o_size + B_ * TOPK_;    // [B, H, W]

    // Threshold: numpy float32 pairwise sum of (cd*cmask) over 11x11,
    // thr = double(sum)/81.0, compare value = float(-thr - 1.0)
    float a[121];
    for (int i = 0; i < 11; i++)
        for (int j = 0; j < 11; j++) {
            int di = i - 5, dj = j - 5;
            int r2 = di * di + dj * dj;
            a[i * 11 + j] = (r2 <= 25) ? sqrtf((float)r2) : 0.0f;
        }
    float r[8];
    for (int k = 0; k < 8; k++) r[k] = a[k];
    int i = 8;
    for (; i < 120; i += 8)
        for (int k = 0; k < 8; k++) r[k] += a[i + k];
    float res = ((r[0] + r[1]) + (r[2] + r[3])) + ((r[4] + r[5]) + (r[6] + r[7]));
    for (; i < 121; i++) res += a[i];
    double thr = (double)res / 81.0;
    float thrF = (float)(-thr - 1.0);

    k_seg<<<dim3(HW_ / 256, B_), 256>>>(logits, o_seg);
    k_vote<<<dim3(W_ / 32, H_ / 8, B_), dim3(32, 8)>>>(regs);
    k_pool<<<dim3(W_ / 32, H_ / 8, B_), dim3(32, 8)>>>(thrF, o_seg, o_cmap, o_inst);
    k_select<<<B_, 1024>>>(o_cmap, o_cent, o_tv);
    k_argmin<<<dim3(ABLK_, B_), 256>>>(regs, o_seg, o_inst, o_cls, o_size);
    k_prob<<<dim3(ABLK_, B_), 256>>>(logits, o_inst, o_size, o_prob);
}

// round 15
// speedup vs baseline: 1.5323x; 1.0236x over previous
#include <cuda_runtime.h>
#include <math.h>
#include <math_constants.h>

#define H_ 512
#define W_ 1024
#define HW_ (H_*W_)
#define B_ 2
#define C_ 34
#define TOPK_ 200
#define MAXK_ 5888
#define SURV_ 4096

// ---------------- scratch ----------------
__device__ float g_vote[B_*HW_];
__device__ float g_m[B_*HW_];
__device__ float g_s[B_*HW_];
__device__ int   g_cnt[B_];
__device__ float g_kval[B_*MAXK_];
__device__ int   g_kidx[B_*MAXK_];
__device__ float g_tv[B_*TOPK_];
__device__ int   g_ti[B_*TOPK_];
__device__ float g_ca[B_*TOPK_];
__device__ float g_cb[B_*TOPK_];
__device__ float g_cc[B_*TOPK_];
__device__ int   g_counts[B_*TOPK_*C_];
__device__ int   g_cls[B_*TOPK_];
__device__ float g_psum[B_*TOPK_];
__device__ int   g_tcnt[B_];
__device__ int   g_tlist[B_*HW_];
__device__ float g_sfv[B_*SURV_];
__device__ int   g_sfi[B_*SURV_];
__device__ int   g_doneD, g_doneE;

// ---------------- K1: seg — R2 scalar branch-free body (+init fold) ----------------
__global__ __launch_bounds__(256) void k_seg(const float* __restrict__ logits,
                                             float* __restrict__ o_seg) {
    int b = blockIdx.y;
    int tid = threadIdx.x;
    if (blockIdx.x == 0 && b == 0) {   // init fold (consumers are later launches)
        for (int i = tid; i < B_*TOPK_*C_; i += 256) g_counts[i] = 0;
        for (int i = tid; i < B_*TOPK_;    i += 256) g_psum[i] = 0.f;
        if (tid < B_) { g_cnt[tid] = 0; g_tcnt[tid] = 0; }
        if (tid == 0) { g_doneD = 0; g_doneE = 0; }
    }
    int pix = blockIdx.x * 256 + tid;
    const float* base = logits + (size_t)b * C_ * HW_ + pix;
    float v[C_];
    #pragma unroll
    for (int c = 0; c < C_; c++) v[c] = base[(size_t)c * HW_];
    float m = v[0]; int bi = 0;
    #pragma unroll
    for (int c = 1; c < C_; c++) if (v[c] > m) { m = v[c]; bi = c; }
    float s = 0.f;
    #pragma unroll
    for (int c = 0; c < C_; c++) s += expf(v[c] - m);
    int idx = b * HW_ + pix;
    o_seg[idx] = (float)bi;
    g_m[idx] = m;
    g_s[idx] = s;
}

// ---------------- K2: vote map (exact op order) ----------------
__global__ __launch_bounds__(256) void k_vote(const float* __restrict__ reg) {
    __shared__ float2 S[18][43];
    int b = blockIdx.z;
    int ox0 = blockIdx.x * 32, oy0 = blockIdx.y * 8;
    const float* r0 = reg + (size_t)b * 2 * HW_;
    const float* r1 = r0 + HW_;
    int tid = threadIdx.y * 32 + threadIdx.x;
    for (int t = tid; t < 18 * 42; t += 256) {
        int rr = t / 42, cc = t % 42;
        int gy = oy0 + rr - 5, gx = ox0 + cc - 5;
        float vx = 0.f, vy = 0.f;
        if (gy >= 0 && gy < H_ && gx >= 0 && gx < W_) {
            int q = gy * W_ + gx;
            vx = r0[q]; vy = r1[q];
        }
        S[rr][cc] = make_float2(vx, vy);
    }
    __syncthreads();
    int tx = threadIdx.x, ty = threadIdx.y;
    float acc = 0.f;
    #pragma unroll
    for (int i = 0; i < 11; i++) {
        #pragma unroll
        for (int j = 0; j < 11; j++) {
            const int di = i - 5, dj = j - 5;
            if (di*di + dj*dj <= 25) {
                float2 v = S[ty + i][tx + j];
                float dx = __fsub_rn((float)dj, v.x);
                float dy = __fsub_rn((float)di, v.y);
                float t2 = __fadd_rn(__fmul_rn(dx, dx), __fmul_rn(dy, dy));
                acc = __fadd_rn(acc, __fsqrt_rn(t2));
            }
        }
    }
    float t = __fdiv_rn(acc, 81.0f);
    g_vote[b * HW_ + (oy0 + ty) * W_ + ox0 + tx] = __fadd_rn(-t, -1.0f);
}

// ---------------- K3: 7x7 max-pool + keep + candidate list + things fold ----------------
__global__ __launch_bounds__(256) void k_pool(float thrF,
                                              const float* __restrict__ o_seg,
                                              float* __restrict__ o_cmap,
                                              float* __restrict__ o_inst) {
    __shared__ float T[14][39];
    int b = blockIdx.z;
    int ox0 = blockIdx.x * 32, oy0 = blockIdx.y * 8;
    int tid = threadIdx.y * 32 + threadIdx.x;
    for (int t = tid; t < 14 * 38; t += 256) {
        int rr = t / 38, cc = t % 38;
        int gy = oy0 + rr - 3, gx = ox0 + cc - 3;
        T[rr][cc] = (gy >= 0 && gy < H_ && gx >= 0 && gx < W_)
                    ? g_vote[b * HW_ + gy * W_ + gx] : -CUDART_INF_F;
    }
    __syncthreads();
    int tx = threadIdx.x, ty = threadIdx.y;
    float v = T[ty + 3][tx + 3];
    float m = -CUDART_INF_F;
    #pragma unroll
    for (int i = 0; i < 7; i++)
        #pragma unroll
        for (int j = 0; j < 7; j++)
            m = fmaxf(m, T[ty + i][tx + j]);
    bool keep = (m == v) && (v > thrF);
    int pix = (oy0 + ty) * W_ + ox0 + tx;
    o_cmap[b * HW_ + pix] = keep ? v : 0.f;
    if (keep) {
        int p = atomicAdd(&g_cnt[b], 1);
        if (p < MAXK_) { g_kval[b * MAXK_ + p] = v; g_kidx[b * MAXK_ + p] = pix; }
    }
    // ---- things fold: 1 px/thread, same pixel as pool output ----
    float sc = o_seg[b * HW_ + pix];
    bool things = (sc > 23.99f) && (sc <= 33.0f);
    o_inst[b * HW_ + pix] = 0.f;           // things px overwritten later by argmin
    unsigned ball = __ballot_sync(0xffffffffu, things);
    if (ball == 0) return;
    int lane = tid & 31;
    int leader = __ffs(ball) - 1;
    int prefix = __popc(ball & ((1u << lane) - 1u));
    int baseI = 0;
    if (lane == leader) baseI = atomicAdd(&g_tcnt[b], __popc(ball));
    baseI = __shfl_sync(0xffffffffu, baseI, leader);
    if (things) g_tlist[b * HW_ + baseI + prefix] = pix;
}

// ---------------- K4: radix-select top-200 (1024 threads) + rank + centers ----------------
// All candidate votes are negative floats: ascending uint bits == descending float.
__global__ __launch_bounds__(1024) void k_select(const float* __restrict__ o_cmap,
                                                 float* __restrict__ o_cent,
                                                 float* __restrict__ o_tv) {
    __shared__ float sv[MAXK_];
    __shared__ int   si[MAXK_];
    __shared__ unsigned hist[256];
    __shared__ unsigned wsum[8];
    __shared__ unsigned sh_pref, sh_want;
    __shared__ int sh_scnt;
    int b = blockIdx.x;
    int tid = threadIdx.x;
    int lane = tid & 31, wid = tid >> 5;
    int n = g_cnt[b];
    if (n > MAXK_) n = MAXK_;
    for (int i = tid; i < n; i += 1024) {
        sv[i] = g_kval[b * MAXK_ + i];
        si[i] = g_kidx[b * MAXK_ + i];
    }
    if (tid == 0) { sh_scnt = 0; sh_want = TOPK_; }
    __syncthreads();

    // ---- exact threshold key T (200th smallest uint key) ----
    unsigned T;
    if (n <= TOPK_) {
        T = 0xFFFFFFFFu;
    } else {
        unsigned prefmask = 0, prefval = 0;
        for (int round = 0; round < 4; round++) {
            int shift = 24 - 8 * round;
            if (tid < 256) hist[tid] = 0;
            __syncthreads();
            for (int i = tid; i < n; i += 1024) {
                unsigned u = __float_as_uint(sv[i]);
                if ((u & prefmask) == prefval)
                    atomicAdd(&hist[(u >> shift) & 255], 1u);
            }
            __syncthreads();
            // 256-thread cooperative inclusive scan over the bins
            unsigned h = 0, x = 0;
            if (tid < 256) {
                h = hist[tid];
                x = h;
                #pragma unroll
                for (int off = 1; off < 32; off <<= 1) {
                    unsigned y = __shfl_up_sync(0xffffffffu, x, off);
                    if (lane >= off) x += y;
                }
                if (lane == 31) wsum[wid] = x;
            }
            __syncthreads();
            if (tid == 0) {
                unsigned c = 0;
                #pragma unroll
                for (int w = 0; w < 8; w++) { unsigned t = wsum[w]; wsum[w] = c; c += t; }
            }
            __syncthreads();
            unsigned want = sh_want;
            unsigned incl = 0, excl = 0;
            if (tid < 256) { incl = x + wsum[wid]; excl = incl - h; }
            __syncthreads();                 // all reads of sh_want done
            if (tid < 256 && excl < want && want <= incl) {   // exactly one thread
                sh_pref = prefval | ((unsigned)tid << shift);
                sh_want = want - excl;
            }
            __syncthreads();
            prefval = sh_pref;
            prefmask |= (0xFFu << shift);
        }
        T = prefval;
    }

    // ---- collect survivors (key <= T) ----
    for (int i = tid; i < n; i += 1024) {
        unsigned u = __float_as_uint(sv[i]);
        if (u <= T) {
            int p = atomicAdd(&sh_scnt, 1);
            if (p < SURV_) { g_sfv[b * SURV_ + p] = sv[i]; g_sfi[b * SURV_ + p] = si[i]; }
        }
    }
    __syncthreads();
    int s = sh_scnt;
    if (s > SURV_) s = SURV_;
    for (int i = tid; i < s; i += 1024) {
        sv[i] = g_sfv[b * SURV_ + i];
        si[i] = g_sfi[b * SURV_ + i];
    }
    __syncthreads();

    // ---- exact rank among survivors (value desc, index asc — jax tie rule) ----
    for (int i = tid; i < s; i += 1024) {
        unsigned ui = __float_as_uint(sv[i]);
        int idi = si[i];
        int r = 0;
        for (int j = 0; j < s; j++) {
            unsigned uj = __float_as_uint(sv[j]);
            r += (uj < ui) || (uj == ui && si[j] < idi);
        }
        if (r < TOPK_) { g_tv[b * TOPK_ + r] = sv[i]; g_ti[b * TOPK_ + r] = idi; }
    }
    __syncthreads();

    // ---- -inf fill (jax pads lowest-index non-keep positions) ----
    int nk = (n < TOPK_) ? n : TOPK_;
    if (tid == 0 && nk < TOPK_) {
        const float* cm = o_cmap + (size_t)b * HW_;
        int slot = nk;
        for (int idx = 0; idx < HW_ && slot < TOPK_; idx++) {
            if (cm[idx] == 0.f) {
                g_tv[b * TOPK_ + slot] = -CUDART_INF_F;
                g_ti[b * TOPK_ + slot] = idx;
                slot++;
            }
        }
    }
    __syncthreads();

    // ---- centers + argmin coefficients ----
    if (tid < TOPK_) {
        float v = g_tv[b * TOPK_ + tid];
        int id = g_ti[b * TOPK_ + tid];
        int ys = id / W_, xs = id % W_;
        o_cent[(b * TOPK_ + tid) * 2 + 0] = (float)ys;
        o_cent[(b * TOPK_ + tid) * 2 + 1] = (float)xs;
        o_tv[b * TOPK_ + tid] = v;
        bool valid = isfinite(v);
        float cx = valid ? (float)xs : 1e9f;
        float cy = valid ? (float)ys : 1e9f;
        g_ca[b * TOPK_ + tid] = -2.f * cx;
        g_cb[b * TOPK_ + tid] = -2.f * cy;
        g_cc[b * TOPK_ + tid] = cx * cx + cy * cy;
    }
}

// ---------------- K5: argmin over 200 centers + fused histogram + (last block) class/size ----------------
#define ABLK_ (HW_ / 256)
__global__ __launch_bounds__(256) void k_argmin(const float* __restrict__ reg,
                                                const float* __restrict__ o_seg,
                                                float* __restrict__ o_inst,
                                                float* __restrict__ o_cls,
                                                float* __restrict__ o_size) {
    __shared__ float4 Ctr[TOPK_];
    int b = blockIdx.y;
    int tid = threadIdx.x;
    if (tid < TOPK_)
        Ctr[tid] = make_float4(g_ca[b * TOPK_ + tid], g_cb[b * TOPK_ + tid],
                               g_cc[b * TOPK_ + tid], 0.f);
    __syncthreads();
    int n = g_tcnt[b];
    int i = blockIdx.x * 256 + tid;
    int inst = 0, cls = 0;
    if (i < n) {
        int pix = g_tlist[b * HW_ + i];
        int y = pix >> 10, x = pix & 1023;
        const float* r0 = reg + (size_t)b * 2 * HW_;
        float px = (float)(x + 1) - r0[pix];
        float py = (float)(y + 1) - r0[HW_ + pix];
        float best = CUDART_INF_F; int bi = 0;
        #pragma unroll 10
        for (int k = 0; k < TOPK_; k++) {
            float4 c = Ctr[k];
            float t = __fmaf_rn(c.x, px, __fmaf_rn(c.y, py, c.z));
            if (t < best) { best = t; bi = k; }
        }
        o_inst[b * HW_ + pix] = (float)(bi + 1);
        inst = bi + 1;
        cls = (int)o_seg[b * HW_ + pix];
    }
    int key = inst * 64 + cls;
    unsigned peers = __match_any_sync(0xffffffffu, key);
    int lane = tid & 31;
    if (inst > 0 && lane == (__ffs(peers) - 1))
        atomicAdd(&g_counts[(b * TOPK_ + inst - 1) * C_ + cls], __popc(peers));
    // ---- last-block fold: class argmax + size ----
    __syncthreads();
    __shared__ int isLast;
    __threadfence();
    if (tid == 0) isLast = (atomicAdd(&g_doneD, 1) == ABLK_ * B_ - 1);
    __syncthreads();
    if (!isLast) return;
    __threadfence();
    for (int t = tid; t < B_ * TOPK_; t += 256) {
        const int* base = &g_counts[t * C_];
        int sum = 0, best = -1, bi = 0;
        #pragma unroll
        for (int c = 0; c < C_; c++) {
            int cnt = base[c];
            sum += cnt;
            if (cnt > best) { best = cnt; bi = c; }
        }
        o_cls[t]  = (float)bi;
        o_size[t] = (float)sum;
        g_cls[t]  = bi;
    }
}

// ---------------- K6: per-instance prob sums + (last block) finalize ----------------
__global__ __launch_bounds__(256) void k_prob(const float* __restrict__ logits,
                                              const float* __restrict__ o_inst,
                                              const float* __restrict__ o_size,
                                              float* __restrict__ o_prob) {
    int b = blockIdx.y;
    int n = g_tcnt[b];
    int tid = threadIdx.x;
    int i = blockIdx.x * 256 + tid;
    int inst = 0;
    float p = 0.f;
    if (i < n) {
        int pix = g_tlist[b * HW_ + i];
        int idx = b * HW_ + pix;
        inst = (int)o_inst[idx];
        int c = g_cls[b * TOPK_ + inst - 1];
        float l = logits[((size_t)b * C_ + c) * HW_ + pix];
        p = expf(l - g_m[idx]) / g_s[idx];
    }
    unsigned peers = __match_any_sync(0xffffffffu, inst);
    int lane = tid & 31;
    int leader = __ffs(peers) - 1;
    float tot = 0.f;
    #pragma unroll
    for (int k = 0; k < 32; k++) {
        float pk = __shfl_sync(0xffffffffu, p, k);
        if (peers & (1u << k)) tot += pk;
    }
    if (inst > 0 && lane == leader)
        atomicAdd(&g_psum[b * TOPK_ + inst - 1], tot);
    // ---- last-block fold: finalize inst_seg_prob ----
    __syncthreads();
    __shared__ int isLast;
    __threadfence();
    if (tid == 0) isLast = (atomicAdd(&g_doneE, 1) == ABLK_ * B_ - 1);
    __syncthreads();
    if (!isLast) return;
    __threadfence();
    for (int t = tid; t < B_ * TOPK_; t += 256)
        o_prob[t] = g_psum[t] / fmaxf(o_size[t], 1.f);
}

// ---------------- host ----------------
extern "C" void kernel_launch(void* const* d_in, const int* in_sizes, int n_in,
                              void* d_out, int out_size) {
    const float* logits = (const float*)d_in[0];
    const float* regs   = (const float*)d_in[2];
    float* out = (float*)d_out;

    float* o_inst = out;                    // [B, H, W]
    float* o_seg  = out + 2 * HW_;          // [B, H, W]
    float* o_cent = out + 4 * HW_;          // [B, 200, 2]
    float* o_tv   = o_cent + B_ * TOPK_ * 2;// [B, 200]
    float* o_cls  = o_tv   + B_ * TOPK_;    // [B, 200]
    float* o_prob = o_cls  + B_ * TOPK_;    // [B, 200]
    float* o_size = o_prob + B_ * TOPK_;    // [B, 200]
    float* o_cmap = o_size + B_ * TOPK_;    // [B, H, W]

    // Threshold: numpy float32 pairwise sum of (cd*cmask) over 11x11,
    // thr = double(sum)/81.0, compare value = float(-thr - 1.0)
    float a[121];
    for (int i = 0; i < 11; i++)
        for (int j = 0; j < 11; j++) {
            int di = i - 5, dj = j - 5;
            int r2 = di * di + dj * dj;
            a[i * 11 + j] = (r2 <= 25) ? sqrtf((float)r2) : 0.0f;
        }
    float r[8];
    for (int k = 0; k < 8; k++) r[k] = a[k];
    int i = 8;
    for (; i < 120; i += 8)
        for (int k = 0; k < 8; k++) r[k] += a[i + k];
    float res = ((r[0] + r[1]) + (r[2] + r[3])) + ((r[4] + r[5]) + (r[6] + r[7]));
    for (; i < 121; i++) res += a[i];
    double thr = (double)res / 81.0;
    float thrF = (float)(-thr - 1.0);

    // Lazily-created side stream + events for the seg || vote fork.
    // Created on the first (non-captured) correctness call; reused for capture.
    // Work per call is identical (deterministic); no device-memory allocation APIs.
    static cudaStream_t s_vote = nullptr;
    static cudaEvent_t  e_fork = nullptr, e_join = nullptr;
    if (s_vote == nullptr) {
        cudaStreamCreateWithFlags(&s_vote, cudaStreamNonBlocking);
        cudaEventCreateWithFlags(&e_fork, cudaEventDisableTiming);
        cudaEventCreateWithFlags(&e_join, cudaEventDisableTiming);
    }

    // fork: vote on side stream, seg on main stream (independent; each keeps
    // its own register/occupancy configuration — unlike the failed block fusion)
    cudaEventRecord(e_fork, 0);
    cudaStreamWaitEvent(s_vote, e_fork, 0);
    k_vote<<<dim3(W_ / 32, H_ / 8, B_), dim3(32, 8), 0, s_vote>>>(regs);
    k_seg<<<dim3(HW_ / 256, B_), 256>>>(logits, o_seg);
    cudaEventRecord(e_join, s_vote);
    cudaStreamWaitEvent(0, e_join, 0);

    // join: pool consumes both vote (g_vote) and seg (o_seg)
    k_pool<<<dim3(W_ / 32, H_ / 8, B_), dim3(32, 8)>>>(thrF, o_seg, o_cmap, o_inst);
    k_select<<<B_, 1024>>>(o_cmap, o_cent, o_tv);
    k_argmin<<<dim3(ABLK_, B_), 256>>>(regs, o_seg, o_inst, o_cls, o_size);
    k_prob<<<dim3(ABLK_, B_), 256>>>(logits, o_inst, o_size, o_prob);
}